// round 10
// baseline (speedup 1.0000x reference)
#include <cuda_runtime.h>

// out[r] = dot(x[r], w_avg) + b_avg   (mean of linear == linear of mean)
//
// Final config: R7 recipe (best measured: main 29.12us / 74.3% DRAM — the
// established HBM ceiling for this 10:1 R/W stream; R9's controlled .cs
// experiment showed cache hints are neutral) with block=128:
//   npairs = 2,000,000 = 128 * 15625 EXACT -> no tail predicate, no clamp,
//   unpredicated store; 13 CTAs/SM residency at 39 regs (52 warps vs 48).
// Frozen elements: 5x float4 x-loads issued FIRST (plain caching), per-warp
// param reduction + __syncwarp only, coefs smem -> registers via 3x LDS.128,
// fully register-resident FMA chain.

__global__ __launch_bounds__(128) void forest_r10_kernel(
    const float4* __restrict__ x4,   // x as float4; 5 per row-pair
    const float*  __restrict__ W,    // [10, 1, 10]
    const float*  __restrict__ b,    // [10, 1]
    float2* __restrict__ out2) {     // out as float2; 1 per row-pair
    __shared__ __align__(16) float sc[4][12];   // per-warp: c0..c9, bias, pad

    const int warp = threadIdx.x >> 5;
    const int lane = threadIdx.x & 31;
    const int t = blockIdx.x * blockDim.x + threadIdx.x;   // exact: no tail

    // ---- 1. x loads first: out to DRAM immediately (~600cyc to hide) ----
    const float4* p = x4 + (size_t)t * 5;
    float4 v0 = p[0];
    float4 v1 = p[1];
    float4 v2 = p[2];
    float4 v3 = p[3];
    float4 v4 = p[4];

    // ---- 2. per-warp param reduction (440B, L1-hit), overlaps x latency ----
    if (lane < 11) {
        float s = 0.f;
        if (lane < 10) {
#pragma unroll
            for (int e = 0; e < 10; ++e) s += W[e * 10 + lane];
        } else {
#pragma unroll
            for (int e = 0; e < 10; ++e) s += b[e];
        }
        sc[warp][lane] = s * 0.1f;
    }
    __syncwarp();   // warp-local; no cross-warp coupling

    // ---- 3. coefs smem -> registers: 3 x LDS.128 ----
    const float4 ca = *reinterpret_cast<const float4*>(&sc[warp][0]); // c0..c3
    const float4 cb = *reinterpret_cast<const float4*>(&sc[warp][4]); // c4..c7
    const float4 cd = *reinterpret_cast<const float4*>(&sc[warp][8]); // c8,c9,bias,pad

    // Row 0 = {v0.xyzw, v1.xyzw, v2.xy}
    float r0 = v0.x * ca.x;
    r0 = fmaf(v0.y, ca.y, r0);
    r0 = fmaf(v0.z, ca.z, r0);
    r0 = fmaf(v0.w, ca.w, r0);
    r0 = fmaf(v1.x, cb.x, r0);
    r0 = fmaf(v1.y, cb.y, r0);
    r0 = fmaf(v1.z, cb.z, r0);
    r0 = fmaf(v1.w, cb.w, r0);
    r0 = fmaf(v2.x, cd.x, r0);
    r0 = fmaf(v2.y, cd.y, r0);

    // Row 1 = {v2.zw, v3.xyzw, v4.xyzw}
    float r1 = v2.z * ca.x;
    r1 = fmaf(v2.w, ca.y, r1);
    r1 = fmaf(v3.x, ca.z, r1);
    r1 = fmaf(v3.y, ca.w, r1);
    r1 = fmaf(v3.z, cb.x, r1);
    r1 = fmaf(v3.w, cb.y, r1);
    r1 = fmaf(v4.x, cb.z, r1);
    r1 = fmaf(v4.y, cb.w, r1);
    r1 = fmaf(v4.z, cd.x, r1);
    r1 = fmaf(v4.w, cd.y, r1);

    out2[t] = make_float2(r0 + cd.z, r1 + cd.z);
}

extern "C" void kernel_launch(void* const* d_in, const int* in_sizes, int n_in,
                              void* d_out, int out_size) {
    const float* x = (const float*)d_in[0];   // [B, 10]
    const float* W = (const float*)d_in[1];   // [10, 1, 10]
    const float* b = (const float*)d_in[2];   // [10, 1]

    int B = in_sizes[0] / 10;                 // 4,000,000
    int npairs = B / 2;                       // 2,000,000

    int threads = 128;                         // 2,000,000 = 128 * 15625 exact
    int blocks = npairs / threads;             // 15625
    if (blocks * threads < npairs) blocks += 1;  // safety (never for B=4M)

    forest_r10_kernel<<<blocks, threads>>>(
        (const float4*)x, W, b, (float2*)d_out);
}

// round 11
// speedup vs baseline: 1.0092x; 1.0092x over previous
#include <cuda_runtime.h>

// out[r] = dot(x[r], w_avg) + b_avg   (mean of linear == linear of mean)
//
// FINAL: exact R7 configuration — the measured argmin across the full
// experiment matrix (R1..R10). Controlled variations proved neutral/worse:
//   - occupancy 49..84% -> DRAM pinned 73-74% (HBM read/write-turnaround
//     ceiling for this 10:1 stream, ~5.9 TB/s at NAT clocks)
//   - .cs cache hints: neutral (R9)
//   - tail-free blocks 128/320: neutral/worse (R8/R10)
//   - persistent grid, SHFL prologue, CTA-wide BAR, LDS-fed FMAs: all worse
// Recipe: 5x float4 x-loads issued FIRST (plain caching), per-warp param
// reduction + __syncwarp only, coefs smem -> registers via 3x LDS.128,
// register-resident FMA chain, predicated float2 store. 176MB total traffic
// is mathematically minimal (algebraic collapse of 10 GEMMs to one dot).

__global__ __launch_bounds__(256) void forest_final_kernel(
    const float4* __restrict__ x4,   // x as float4; 5 per row-pair
    const float*  __restrict__ W,    // [10, 1, 10]
    const float*  __restrict__ b,    // [10, 1]
    float2* __restrict__ out2,       // out as float2; 1 per row-pair
    int npairs) {
    __shared__ __align__(16) float sc[8][12];   // per-warp: c0..c9, bias, pad

    const int warp = threadIdx.x >> 5;
    const int lane = threadIdx.x & 31;

    const int t = blockIdx.x * blockDim.x + threadIdx.x;
    const bool active = (t < npairs);
    const int tc = active ? t : (npairs - 1);   // clamp tail

    // ---- 1. x loads first: out to DRAM immediately (~600cyc to hide) ----
    const float4* p = x4 + (size_t)tc * 5;
    float4 v0 = p[0];
    float4 v1 = p[1];
    float4 v2 = p[2];
    float4 v3 = p[3];
    float4 v4 = p[4];

    // ---- 2. per-warp param reduction (440B, L1-hit), overlaps x latency ----
    if (lane < 11) {
        float s = 0.f;
        if (lane < 10) {
#pragma unroll
            for (int e = 0; e < 10; ++e) s += W[e * 10 + lane];
        } else {
#pragma unroll
            for (int e = 0; e < 10; ++e) s += b[e];
        }
        sc[warp][lane] = s * 0.1f;
    }
    __syncwarp();   // warp-local; no cross-warp coupling

    // ---- 3. coefs smem -> registers: 3 x LDS.128 ----
    const float4 ca = *reinterpret_cast<const float4*>(&sc[warp][0]); // c0..c3
    const float4 cb = *reinterpret_cast<const float4*>(&sc[warp][4]); // c4..c7
    const float4 cd = *reinterpret_cast<const float4*>(&sc[warp][8]); // c8,c9,bias,pad

    // Row 0 = {v0.xyzw, v1.xyzw, v2.xy}
    float r0 = v0.x * ca.x;
    r0 = fmaf(v0.y, ca.y, r0);
    r0 = fmaf(v0.z, ca.z, r0);
    r0 = fmaf(v0.w, ca.w, r0);
    r0 = fmaf(v1.x, cb.x, r0);
    r0 = fmaf(v1.y, cb.y, r0);
    r0 = fmaf(v1.z, cb.z, r0);
    r0 = fmaf(v1.w, cb.w, r0);
    r0 = fmaf(v2.x, cd.x, r0);
    r0 = fmaf(v2.y, cd.y, r0);

    // Row 1 = {v2.zw, v3.xyzw, v4.xyzw}
    float r1 = v2.z * ca.x;
    r1 = fmaf(v2.w, ca.y, r1);
    r1 = fmaf(v3.x, ca.z, r1);
    r1 = fmaf(v3.y, ca.w, r1);
    r1 = fmaf(v3.z, cb.x, r1);
    r1 = fmaf(v3.w, cb.y, r1);
    r1 = fmaf(v4.x, cb.z, r1);
    r1 = fmaf(v4.y, cb.w, r1);
    r1 = fmaf(v4.z, cd.x, r1);
    r1 = fmaf(v4.w, cd.y, r1);

    if (active) {
        out2[t] = make_float2(r0 + cd.z, r1 + cd.z);
    }
}

extern "C" void kernel_launch(void* const* d_in, const int* in_sizes, int n_in,
                              void* d_out, int out_size) {
    const float* x = (const float*)d_in[0];   // [B, 10]
    const float* W = (const float*)d_in[1];   // [10, 1, 10]
    const float* b = (const float*)d_in[2];   // [10, 1]

    int B = in_sizes[0] / 10;                 // 4,000,000
    int npairs = B / 2;                       // B is even

    int threads = 256;
    int blocks = (npairs + threads - 1) / threads;
    forest_final_kernel<<<blocks, threads>>>(
        (const float4*)x, W, b, (float2*)d_out, npairs);
}